// round 10
// baseline (speedup 1.0000x reference)
#include <cuda_runtime.h>
#include <cuda_fp16.h>
#include <cstdint>
#include <cstddef>
#include <math.h>

#define SQ  512
#define HID 2048
#define NZ  64
#define MR  8192

static const float SCALE_F = 0.04419417382415922f;

// ------------------------- scratch -------------------------
__device__ __align__(1024) __half g_xh  [(size_t)MR*HID];
__device__ __align__(1024) __half g_x2  [(size_t)MR*2*HID];
__device__ __align__(1024) __half g_wh  [(size_t)5*HID*HID];
__device__ __align__(1024) __half g_w2  [(size_t)5*HID*2*HID];
__device__ __align__(1024) float  g_c1p [(size_t)5*MR*HID];
__device__ __align__(1024) float  g_c1a [(size_t)NZ*SQ*SQ];
__device__ __align__(1024) float  g_ypv [(size_t)MR*HID];
__device__ __align__(1024) float  g_ypcv[(size_t)MR*HID];
__device__ __align__(1024) float  g_s2  [(size_t)NZ*SQ*SQ];
__device__ __align__(1024) __half g_qh  [(size_t)NZ*SQ*SQ];
__device__ __align__(1024) __half g_q2  [(size_t)NZ*SQ*2*SQ];
__device__ __align__(1024) __half g_kh  [(size_t)NZ*SQ*SQ];
__device__ __align__(1024) __half g_k2  [(size_t)NZ*SQ*2*SQ];
__device__ __align__(1024) __half g_ckh [(size_t)NZ*SQ*SQ];
__device__ __align__(1024) __half g_ck2 [(size_t)NZ*SQ*2*SQ];
__device__ __align__(1024) __half g_vTh [(size_t)NZ*SQ*SQ];
__device__ __align__(1024) __half g_vT2 [(size_t)NZ*SQ*2*SQ];
__device__ __align__(1024) __half g_cvTh[(size_t)NZ*SQ*SQ];
__device__ __align__(1024) __half g_cvT2[(size_t)NZ*SQ*2*SQ];
__device__ __align__(1024) __half g_s1h [(size_t)NZ*SQ*SQ];
__device__ __align__(1024) __half g_s12 [(size_t)NZ*SQ*2*SQ];
__device__ __align__(1024) __half g_ph  [(size_t)NZ*SQ*SQ];
__device__ __align__(1024) __half g_p2  [(size_t)NZ*SQ*2*SQ];
__device__ __align__(1024) __half g_ch  [(size_t)NZ*SQ*SQ];
__device__ __align__(1024) __half g_c2  [(size_t)NZ*SQ*2*SQ];

// ------------------------- helpers -------------------------
#define CP16(dst, src) asm volatile("cp.async.cg.shared.global [%0], [%1], 16;" \
    :: "r"(dst), "l"(src))
#define CP_COMMIT() asm volatile("cp.async.commit_group;")
#define CP_WAIT(n)  asm volatile("cp.async.wait_group %0;" :: "n"(n))

__device__ __forceinline__ void ldsm4(uint32_t* d, uint32_t addr) {
    asm volatile("ldmatrix.sync.aligned.m8n8.x4.shared.b16 {%0,%1,%2,%3}, [%4];"
        : "=r"(d[0]), "=r"(d[1]), "=r"(d[2]), "=r"(d[3]) : "r"(addr));
}
__device__ __forceinline__ void mma_f32(float* c, const uint32_t* a, uint32_t b0, uint32_t b1) {
    asm volatile("mma.sync.aligned.m16n8k16.row.col.f32.f16.f16.f32 "
        "{%0,%1,%2,%3}, {%4,%5,%6,%7}, {%8,%9}, {%0,%1,%2,%3};"
        : "+f"(c[0]), "+f"(c[1]), "+f"(c[2]), "+f"(c[3])
        : "r"(a[0]), "r"(a[1]), "r"(a[2]), "r"(a[3]), "r"(b0), "r"(b1));
}
__device__ __forceinline__ void mma_f16(uint32_t* c, const uint32_t* a, uint32_t b0, uint32_t b1) {
    asm volatile("mma.sync.aligned.m16n8k16.row.col.f16.f16.f16.f16 "
        "{%0,%1}, {%2,%3,%4,%5}, {%6,%7}, {%0,%1};"
        : "+r"(c[0]), "+r"(c[1])
        : "r"(a[0]), "r"(a[1]), "r"(a[2]), "r"(a[3]), "r"(b0), "r"(b1));
}
__device__ __forceinline__ void splitH2(float x, float y, uint32_t& h2, uint32_t& l2) {
    __half2 h, l;
    h.x = __float2half_rn(x); l.x = __float2half_rn(x - __half2float(h.x));
    h.y = __float2half_rn(y); l.y = __float2half_rn(y - __half2float(h.y));
    h2 = *reinterpret_cast<uint32_t*>(&h);
    l2 = *reinterpret_cast<uint32_t*>(&l);
}

struct P2 { const float* bias[5]; void* oh[5]; void* o2[5]; };
struct WPtr { const float* w[5]; };

// ===================== pass1: f16 in, f32 acc, 128x128 CTA ==================
#define P1_STGB 10240u
#define P1_NSTG 5
#define P1_SMEM (2u * P1_NSTG * P1_STGB)

__global__ __launch_bounds__(256, 2) void gemm_p1(
    const __half* __restrict__ A, long long sAz, int lda,
    const __half* __restrict__ B, long long sBz, int ldb,
    float* __restrict__ C, long long sCz, int ldc, int K)
{
    extern __shared__ char smraw[];
    const uint32_t baseA = (uint32_t)__cvta_generic_to_shared(smraw);
    const uint32_t baseB = baseA + P1_NSTG * P1_STGB;

    const int tid = threadIdx.x;
    const int lane = tid & 31, wid = tid >> 5;
    const int wm = wid >> 2, wn = wid & 3;
    const int m0 = blockIdx.y * 128, n0 = blockIdx.x * 128, z = blockIdx.z;

    const __half* Az = A + (size_t)z * sAz;
    const __half* Bz = B + (size_t)z * sBz;

    const int lr = tid >> 2, lq = tid & 3;
    const __half* gA0 = Az + (size_t)(m0 + lr) * lda + lq * 8;
    const __half* gA1 = Az + (size_t)(m0 + lr + 64) * lda + lq * 8;
    const __half* gB0 = Bz + (size_t)(n0 + lr) * ldb + lq * 8;
    const __half* gB1 = Bz + (size_t)(n0 + lr + 64) * ldb + lq * 8;

    const uint32_t dA0 = baseA + lr * 80 + lq * 16;
    const uint32_t dA1 = baseA + (lr + 64) * 80 + lq * 16;
    const uint32_t dB0 = baseB + lr * 80 + lq * 16;
    const uint32_t dB1 = baseB + (lr + 64) * 80 + lq * 16;

    const int lrow = (lane & 7) + ((lane >> 3) & 1) * 8;
    const int lchunk = lane >> 4;
    const uint32_t aAddr = (wm * 64 + lrow) * 80 + lchunk * 16;
    const uint32_t bAddr = (wn * 32 + lrow) * 80 + lchunk * 16;

    float acc[4][4][4];
#pragma unroll
    for (int i = 0; i < 4; i++)
#pragma unroll
        for (int j = 0; j < 4; j++) { acc[i][j][0]=0.f; acc[i][j][1]=0.f; acc[i][j][2]=0.f; acc[i][j][3]=0.f; }

#define LT1(kt, st) do { \
    const size_t ko = (size_t)(kt) * 32; \
    const uint32_t so = (uint32_t)(st) * P1_STGB; \
    CP16(dA0 + so, gA0 + ko); CP16(dA1 + so, gA1 + ko); \
    CP16(dB0 + so, gB0 + ko); CP16(dB1 + so, gB1 + ko); \
} while (0)
#define CC1(st) do { \
    const uint32_t so = (uint32_t)(st) * P1_STGB; \
    _Pragma("unroll") \
    for (int k16 = 0; k16 < 2; ++k16) { \
        const uint32_t kb = so + k16 * 32; \
        uint32_t a[4][4], bq[2][4]; \
        _Pragma("unroll") \
        for (int mi = 0; mi < 4; ++mi) ldsm4(a[mi], baseA + kb + aAddr + mi * (16*80)); \
        _Pragma("unroll") \
        for (int j = 0; j < 2; ++j) ldsm4(bq[j], baseB + kb + bAddr + j * (16*80)); \
        _Pragma("unroll") \
        for (int mi = 0; mi < 4; ++mi) \
            _Pragma("unroll") \
            for (int ni = 0; ni < 4; ++ni) \
                mma_f32(acc[mi][ni], a[mi], bq[ni >> 1][ni & 1], bq[ni >> 1][2 + (ni & 1)]); \
    } \
} while (0)

    const int KT = K / 32;   // even
    LT1(0, 0); CP_COMMIT();
    LT1(1, 1); CP_COMMIT();
    LT1(2, 2); CP_COMMIT();
    int cs = 0, ls = 3;
    for (int kt = 0; kt < KT; kt += 2) {
        CP_WAIT(1);
        __syncthreads();
        const int ls2 = (ls + 1 == P1_NSTG) ? 0 : ls + 1;
        if (kt + 3 < KT) { LT1(kt + 3, ls); CP_COMMIT(); } else CP_COMMIT();
        if (kt + 4 < KT) { LT1(kt + 4, ls2); CP_COMMIT(); } else CP_COMMIT();
        const int cs2 = (cs + 1 == P1_NSTG) ? 0 : cs + 1;
        CC1(cs); CC1(cs2);
        cs = (cs2 + 1 == P1_NSTG) ? 0 : cs2 + 1;
        ls = (ls2 + 1 == P1_NSTG) ? 0 : ls2 + 1;
    }
#undef LT1
#undef CC1

    float* Cz = C + (size_t)z * sCz;
#pragma unroll
    for (int mi = 0; mi < 4; ++mi)
#pragma unroll
        for (int ni = 0; ni < 4; ++ni) {
            const int r0 = m0 + wm * 64 + mi * 16 + (lane >> 2);
            const int c  = n0 + wn * 32 + ni * 8 + (lane & 3) * 2;
#pragma unroll
            for (int hh = 0; hh < 2; ++hh) {
                float2 f; f.x = acc[mi][ni][hh*2]; f.y = acc[mi][ni][hh*2+1];
                *(float2*)(Cz + (size_t)(r0 + hh * 8) * ldc + c) = f;
            }
        }
}

// ============ pass2: f16 in, f16 acc, 128x256 CTA, warp tile 64x64 ==========
#define P2_ASTG 10240u
#define P2_BSTG 20480u
#define P2_STGB (P2_ASTG + P2_BSTG)
#define P2_NSTG 3
#define P2_SMEM (P2_NSTG * P2_STGB)   // 92160

// EPI 0: fp32 out (v=(c1+acc)*alpha), strided
// EPI 1: attn cat: h->out1 [z][512][512], (h,l)->out2 [z][512][1024]
// EPI 2: proj: v=c1+acc+bias; z==2/4 -> fp32; z==0 A-cat; z==1/3 B-cat (head remap)
template <int EPI>
__global__ __launch_bounds__(256, 2) void gemm_p2(
    const __half* __restrict__ A, long long sAz, int lda,
    const __half* __restrict__ B, long long sBz, int ldb,
    const float* __restrict__ c1, long long c1sZ, int c1ld,
    void* out1, void* out2, float alpha, int K,
    long long sCb, long long sCh, int ldc, P2 pp)
{
    extern __shared__ char smraw[];
    const uint32_t base = (uint32_t)__cvta_generic_to_shared(smraw);

    const int tid = threadIdx.x;
    const int lane = tid & 31, wid = tid >> 5;
    const int wm = wid >> 2, wn = wid & 3;       // warp tile 64(M) x 64(N)
    const int m0 = blockIdx.y * 128, n0 = blockIdx.x * 256, z = blockIdx.z;

    const __half* Az = A + (size_t)z * sAz;
    const __half* Bz = B + (size_t)z * sBz;

    const int arow = tid >> 1;
    const __half* gA = Az + (size_t)(m0 + arow) * lda + (tid & 1) * 16;
    const uint32_t dA = base + arow * 80 + (tid & 1) * 32;
    const __half* gB = Bz + (size_t)(n0 + tid) * ldb;
    const uint32_t dB = base + P2_ASTG + tid * 80;

    const int lrow = (lane & 7) + ((lane >> 3) & 1) * 8;
    const int lchunk = lane >> 4;
    const uint32_t aAddr = (wm * 64 + lrow) * 80 + lchunk * 16;
    const uint32_t bAddr = P2_ASTG + (wn * 64 + lrow) * 80 + lchunk * 16;

    uint32_t acch[4][8][2];
#pragma unroll
    for (int i = 0; i < 4; i++)
#pragma unroll
        for (int j = 0; j < 8; j++) { acch[i][j][0] = 0u; acch[i][j][1] = 0u; }

#define LT2(kt, st) do { \
    const size_t ko = (size_t)(kt) * 32; \
    const uint32_t so = (uint32_t)(st) * P2_STGB; \
    CP16(dA + so, gA + ko); CP16(dA + so + 16, gA + ko + 8); \
    CP16(dB + so,      gB + ko);      CP16(dB + so + 16, gB + ko + 8); \
    CP16(dB + so + 32, gB + ko + 16); CP16(dB + so + 48, gB + ko + 24); \
} while (0)

    const int KT = K / 32;
    LT2(0, 0); CP_COMMIT();
    LT2(1, 1); CP_COMMIT();
    int cs = 0, ls = 2;
    for (int kt = 0; kt < KT; ++kt) {
        CP_WAIT(1);
        __syncthreads();
        if (kt + 2 < KT) { LT2(kt + 2, ls); CP_COMMIT(); } else CP_COMMIT();
        const uint32_t so = (uint32_t)cs * P2_STGB;
#pragma unroll
        for (int k16 = 0; k16 < 2; ++k16) {
            const uint32_t kb = so + k16 * 32;
            uint32_t a[4][4], bq[4][4];
#pragma unroll
            for (int mi = 0; mi < 4; ++mi)
                ldsm4(a[mi], base + kb + aAddr + mi * (16 * 80));
#pragma unroll
            for (int nj = 0; nj < 4; ++nj)
                ldsm4(bq[nj], base + kb + bAddr + nj * (16 * 80));
#pragma unroll
            for (int mi = 0; mi < 4; ++mi)
#pragma unroll
                for (int ni = 0; ni < 8; ++ni)
                    mma_f16(acch[mi][ni], a[mi], bq[ni >> 1][ni & 1], bq[ni >> 1][2 + (ni & 1)]);
        }
        cs = (cs + 1 == P2_NSTG) ? 0 : cs + 1;
        ls = (ls + 1 == P2_NSTG) ? 0 : ls + 1;
    }
#undef LT2

    const float* c1z = c1 + (size_t)z * c1sZ;
    const bool fp32z = (EPI == 2) && (z == 2 || z == 4);
    const bool modeB = (z != 0);

#pragma unroll
    for (int mi = 0; mi < 4; ++mi)
#pragma unroll
        for (int ni = 0; ni < 8; ++ni) {
            const int r0 = m0 + wm * 64 + mi * 16 + (lane >> 2);
            const int c  = n0 + wn * 64 + ni * 8 + (lane & 3) * 2;
#pragma unroll
            for (int hh = 0; hh < 2; ++hh) {
                const int r = r0 + hh * 8;
                __half2 pv = *reinterpret_cast<__half2*>(&acch[mi][ni][hh]);
                float v0 = __half2float(pv.x), v1 = __half2float(pv.y);
                float2 c1v = *(const float2*)(c1z + (size_t)r * c1ld + c);
                v0 += c1v.x; v1 += c1v.y;
                if (EPI == 0) {
                    float2 f; f.x = v0 * alpha; f.y = v1 * alpha;
                    float* o = (float*)out1 + (size_t)(z >> 2) * sCb + (size_t)(z & 3) * sCh
                               + (size_t)r * ldc + c;
                    *(float2*)o = f;
                } else if (EPI == 1) {
                    uint32_t h2, l2; splitH2(v0, v1, h2, l2);
                    __half* oh = (__half*)out1 + (size_t)z * SQ * SQ + (size_t)r * SQ + c;
                    __half* o2 = (__half*)out2 + (size_t)z * SQ * 2 * SQ + (size_t)r * 2 * SQ + c;
                    *(uint32_t*)oh = h2;
                    *(uint32_t*)o2 = h2;
                    *(uint32_t*)(o2 + SQ) = l2;
                } else {
                    v0 += pp.bias[z][c]; v1 += pp.bias[z][c + 1];
                    if (fp32z) {
                        float2 f; f.x = v0; f.y = v1;
                        *(float2*)((float*)pp.oh[z] + (size_t)r * HID + c) = f;
                    } else {
                        uint32_t h2, l2; splitH2(v0, v1, h2, l2);
                        const size_t ih = (size_t)(((r >> 9) << 2) + (c >> 9)) * SQ + (r & 511);
                        const int dl = c & 511;
                        __half* oh = (__half*)pp.oh[z] + ih * SQ + dl;
                        __half* o2 = (__half*)pp.o2[z] + ih * 2 * SQ + dl;
                        *(uint32_t*)oh = h2;
                        *(uint32_t*)o2        = modeB ? l2 : h2;
                        *(uint32_t*)(o2 + SQ) = modeB ? h2 : l2;
                    }
                }
            }
        }
}

// ------------------------- conversions -------------------------
__global__ void conv_xh(const float* __restrict__ in, __half* __restrict__ xh,
                        __half* __restrict__ x2)
{
    const int r = blockIdx.y;
    const int k = (blockIdx.x * blockDim.x + threadIdx.x) * 2;
    float2 x = *(const float2*)(in + (size_t)r * HID + k);
    uint32_t h2, l2; splitH2(x.x, x.y, h2, l2);
    *(uint32_t*)(xh + (size_t)r * HID + k)           = h2;
    *(uint32_t*)(x2 + (size_t)r * 2 * HID + k)       = h2;
    *(uint32_t*)(x2 + (size_t)r * 2 * HID + HID + k) = l2;
}

__global__ void conv_wh(WPtr wp, __half* __restrict__ wh, __half* __restrict__ w2)
{
    const int w = blockIdx.z;
    const int r = blockIdx.y;
    const int k = (blockIdx.x * blockDim.x + threadIdx.x) * 2;
    float2 x = *(const float2*)(wp.w[w] + (size_t)r * HID + k);
    uint32_t h2, l2; splitH2(x.x, x.y, h2, l2);
    *(uint32_t*)(wh + ((size_t)w * HID + r) * HID + k)           = h2;
    *(uint32_t*)(w2 + ((size_t)w * HID + r) * 2 * HID + k)       = l2;
    *(uint32_t*)(w2 + ((size_t)w * HID + r) * 2 * HID + HID + k) = h2;
}

__global__ void convT_head(const float* __restrict__ in,
                           __half* __restrict__ oh, __half* __restrict__ o2)
{
    __shared__ float t[32][33];
    const int r0 = blockIdx.y * 32, c0 = blockIdx.x * 32;
    const int tx = threadIdx.x, ty = threadIdx.y;
#pragma unroll
    for (int i = ty; i < 32; i += 8)
        t[i][tx] = in[(size_t)(r0 + i) * HID + c0 + tx];
    __syncthreads();
#pragma unroll
    for (int i = ty; i < 32; i += 8) {
        float x = t[tx][i];
        const int s = (r0 + tx) & 511;
        const size_t ih = (size_t)(((r0 >> 9) << 2) + ((c0 + i) >> 9)) * SQ + ((c0 + i) & 511);
        __half h = __float2half_rn(x);
        __half l = __float2half_rn(x - __half2float(h));
        oh[ih * SQ + s] = h;
        o2[ih * 2 * SQ + s] = l;           // B-cat [l|h]
        o2[ih * 2 * SQ + SQ + s] = h;
    }
}

__global__ __launch_bounds__(128) void softmax_h(const float* __restrict__ S,
                                                 __half* __restrict__ ph,
                                                 __half* __restrict__ p2)
{
    const size_t row = blockIdx.x;
    const int t = threadIdx.x;
    float4 v = ((const float4*)(S + row * SQ))[t];
    float m = fmaxf(fmaxf(v.x, v.y), fmaxf(v.z, v.w));
#pragma unroll
    for (int o = 16; o; o >>= 1) m = fmaxf(m, __shfl_xor_sync(0xffffffffu, m, o));
    __shared__ float rm[4];
    if ((t & 31) == 0) rm[t >> 5] = m;
    __syncthreads();
    m = fmaxf(fmaxf(rm[0], rm[1]), fmaxf(rm[2], rm[3]));
    v.x = expf(v.x - m); v.y = expf(v.y - m); v.z = expf(v.z - m); v.w = expf(v.w - m);
    float s = v.x + v.y + v.z + v.w;
#pragma unroll
    for (int o = 16; o; o >>= 1) s += __shfl_xor_sync(0xffffffffu, s, o);
    __shared__ float rs[4];
    if ((t & 31) == 0) rs[t >> 5] = s;
    __syncthreads();
    s = rs[0] + rs[1] + rs[2] + rs[3];
    const float inv = 1.0f / s;
    uint32_t h0, l0, h1, l1;
    splitH2(v.x * inv, v.y * inv, h0, l0);
    splitH2(v.z * inv, v.w * inv, h1, l1);
    __half* o = ph + row * SQ + t * 4;
    *(uint32_t*)o = h0; *(uint32_t*)(o + 2) = h1;
    __half* q = p2 + row * 2 * SQ + t * 4;
    *(uint32_t*)q = h0; *(uint32_t*)(q + 2) = h1;
    *(uint32_t*)(q + SQ) = l0; *(uint32_t*)(q + SQ + 2) = l1;
}

// ------------------------- host -------------------------
extern "C" void kernel_launch(void* const* d_in, const int* in_sizes, int n_in,
                              void* d_out, int out_size)
{
    const float* X = (const float*)d_in[0];
    WPtr wp = {{(const float*)d_in[1], (const float*)d_in[3], (const float*)d_in[5],
                (const float*)d_in[7], (const float*)d_in[9]}};
    const float* Bi[5] = {(const float*)d_in[2], (const float*)d_in[4], (const float*)d_in[6],
                          (const float*)d_in[8], (const float*)d_in[10]};

    void *xh, *x2, *wh, *w2, *c1p, *c1a, *ypv, *ypcv, *s2;
    void *qh, *q2, *kh, *k2, *ckh, *ck2, *vTh, *vT2, *cvTh, *cvT2;
    void *s1h, *s12, *ph, *p2, *ch, *c2;
    cudaGetSymbolAddress(&xh, g_xh);     cudaGetSymbolAddress(&x2, g_x2);
    cudaGetSymbolAddress(&wh, g_wh);     cudaGetSymbolAddress(&w2, g_w2);
    cudaGetSymbolAddress(&c1p, g_c1p);   cudaGetSymbolAddress(&c1a, g_c1a);
    cudaGetSymbolAddress(&ypv, g_ypv);   cudaGetSymbolAddress(&ypcv, g_ypcv);
    cudaGetSymbolAddress(&s2, g_s2);
    cudaGetSymbolAddress(&qh, g_qh);     cudaGetSymbolAddress(&q2, g_q2);
    cudaGetSymbolAddress(&kh, g_kh);     cudaGetSymbolAddress(&k2, g_k2);
    cudaGetSymbolAddress(&ckh, g_ckh);   cudaGetSymbolAddress(&ck2, g_ck2);
    cudaGetSymbolAddress(&vTh, g_vTh);   cudaGetSymbolAddress(&vT2, g_vT2);
    cudaGetSymbolAddress(&cvTh, g_cvTh); cudaGetSymbolAddress(&cvT2, g_cvT2);
    cudaGetSymbolAddress(&s1h, g_s1h);   cudaGetSymbolAddress(&s12, g_s12);
    cudaGetSymbolAddress(&ph, g_ph);     cudaGetSymbolAddress(&p2, g_p2);
    cudaGetSymbolAddress(&ch, g_ch);     cudaGetSymbolAddress(&c2, g_c2);

    P2 pp;
    for (int i = 0; i < 5; i++) pp.bias[i] = Bi[i];
    pp.oh[0] = qh;  pp.o2[0] = q2;
    pp.oh[1] = kh;  pp.o2[1] = k2;
    pp.oh[2] = ypv; pp.o2[2] = nullptr;
    pp.oh[3] = ckh; pp.o2[3] = ck2;
    pp.oh[4] = ypcv; pp.o2[4] = nullptr;
    P2 pz = {};

    static bool attr_done = false;
    if (!attr_done) {
        cudaFuncSetAttribute(gemm_p1, cudaFuncAttributeMaxDynamicSharedMemorySize, P1_SMEM);
        cudaFuncSetAttribute(gemm_p2<0>, cudaFuncAttributeMaxDynamicSharedMemorySize, P2_SMEM);
        cudaFuncSetAttribute(gemm_p2<1>, cudaFuncAttributeMaxDynamicSharedMemorySize, P2_SMEM);
        cudaFuncSetAttribute(gemm_p2<2>, cudaFuncAttributeMaxDynamicSharedMemorySize, P2_SMEM);
        attr_done = true;
    }

    const long long sSS = (long long)SQ * SQ;
    const long long s2S = (long long)SQ * 2 * SQ;

    // 0,1: conversions
    conv_xh<<<dim3(8, MR), 128>>>(X, (__half*)xh, (__half*)x2);
    conv_wh<<<dim3(8, HID, 5), 128>>>(wp, (__half*)wh, (__half*)w2);
    // 2: proj pass1  C1 = Xh Wh^T
    gemm_p1<<<dim3(16, 64, 5), 256, P1_SMEM>>>(
        (const __half*)xh, 0LL, HID, (const __half*)wh, (long long)HID * HID, HID,
        (float*)c1p, (long long)MR * HID, HID, HID);
    // 3: proj pass2 (f16 acc) + C1 + bias -> q/k/ck cats, v/cv fp32
    gemm_p2<2><<<dim3(8, 64, 5), 256, P2_SMEM>>>(
        (const __half*)x2, 0LL, 2 * HID, (const __half*)w2, (long long)HID * 2 * HID, 2 * HID,
        (const float*)c1p, (long long)MR * HID, HID,
        nullptr, nullptr, 1.0f, 2 * HID, 0, 0, 0, pp);
    // 4,5: transpose-cats
    convT_head<<<dim3(HID / 32, MR / 32), dim3(32, 8)>>>((const float*)ypv, (__half*)vTh, (__half*)vT2);
    convT_head<<<dim3(HID / 32, MR / 32), dim3(32, 8)>>>((const float*)ypcv, (__half*)cvTh, (__half*)cvT2);
    // 6,7: s1 = q k^T
    gemm_p1<<<dim3(4, 4, 64), 256, P1_SMEM>>>(
        (const __half*)qh, sSS, SQ, (const __half*)kh, sSS, SQ, (float*)c1a, sSS, SQ, SQ);
    gemm_p2<1><<<dim3(2, 4, 64), 256, P2_SMEM>>>(
        (const __half*)q2, s2S, 2 * SQ, (const __half*)k2, s2S, 2 * SQ,
        (const float*)c1a, sSS, SQ, s1h, s12, 1.0f, 2 * SQ, 0, 0, 0, pz);
    // 8,9: s2 = (s1 ck^T) * SCALE
    gemm_p1<<<dim3(4, 4, 64), 256, P1_SMEM>>>(
        (const __half*)s1h, sSS, SQ, (const __half*)ckh, sSS, SQ, (float*)c1a, sSS, SQ, SQ);
    {
        // EPI0 out: s2 + z*SQ*SQ => use sCb=4*SQ*SQ per b (z>>2), sCh=SQ*SQ per h (z&3)
        gemm_p2<0><<<dim3(2, 4, 64), 256, P2_SMEM>>>(
            (const __half*)s12, s2S, 2 * SQ, (const __half*)ck2, s2S, 2 * SQ,
            (const float*)c1a, sSS, SQ, s2, nullptr, SCALE_F, 2 * SQ,
            4LL * SQ * SQ, sSS, SQ, pz);
    }
    // 10: softmax
    softmax_h<<<NZ * SQ, 128>>>((const float*)s2, (__half*)ph, (__half*)p2);
    // 11,12: ctx = P V
    gemm_p1<<<dim3(4, 4, 64), 256, P1_SMEM>>>(
        (const __half*)ph, sSS, SQ, (const __half*)vTh, sSS, SQ, (float*)c1a, sSS, SQ, SQ);
    gemm_p2<1><<<dim3(2, 4, 64), 256, P2_SMEM>>>(
        (const __half*)p2, s2S, 2 * SQ, (const __half*)vT2, s2S, 2 * SQ,
        (const float*)c1a, sSS, SQ, ch, c2, 1.0f, 2 * SQ, 0, 0, 0, pz);
    // 13,14: out = ctx CV -> d_out [b][s][h*512+e]
    gemm_p1<<<dim3(4, 4, 64), 256, P1_SMEM>>>(
        (const __half*)ch, sSS, SQ, (const __half*)cvTh, sSS, SQ, (float*)c1a, sSS, SQ, SQ);
    gemm_p2<0><<<dim3(2, 4, 64), 256, P2_SMEM>>>(
        (const __half*)c2, s2S, 2 * SQ, (const __half*)cvT2, s2S, 2 * SQ,
        (const float*)c1a, sSS, SQ, d_out, nullptr, 1.0f, 2 * SQ,
        (long long)SQ * HID, 512, HID, pz);
}

// round 11
// speedup vs baseline: 1.2767x; 1.2767x over previous
#include <cuda_runtime.h>
#include <cuda_fp16.h>
#include <cstdint>
#include <cstddef>
#include <math.h>

#define SQ  512
#define HID 2048
#define NZ  64
#define MR  8192
#define K3A 1536
#define K2A 1024
#define K3P 6144
#define K2P 4096

static const float SCALE_F = 0.04419417382415922f;

// ------------------------- scratch -------------------------
__device__ __align__(1024) __half g_x3  [(size_t)MR*K3P];
__device__ __align__(1024) __half g_x2  [(size_t)MR*K2P];
__device__ __align__(1024) __half g_w3  [(size_t)3*HID*K3P];
__device__ __align__(1024) __half g_w2  [(size_t)2*HID*K2P];
__device__ __align__(1024) float  g_ypv [(size_t)MR*HID];
__device__ __align__(1024) float  g_ypcv[(size_t)MR*HID];
__device__ __align__(1024) __half g_q3  [(size_t)NZ*SQ*K3A];
__device__ __align__(1024) __half g_k3  [(size_t)NZ*SQ*K3A];
__device__ __align__(1024) __half g_ck3 [(size_t)NZ*SQ*K3A];
__device__ __align__(1024) __half g_vT2 [(size_t)NZ*SQ*K2A];
__device__ __align__(1024) __half g_cvT2[(size_t)NZ*SQ*K2A];
__device__ __align__(1024) __half g_s13 [(size_t)NZ*SQ*K3A];
__device__ __align__(1024) float  g_s2  [(size_t)NZ*SQ*SQ];
__device__ __align__(1024) __half g_p2  [(size_t)NZ*SQ*K2A];
__device__ __align__(1024) __half g_c2  [(size_t)NZ*SQ*K2A];

// ------------------------- helpers -------------------------
#define CP16(dst, src) asm volatile("cp.async.cg.shared.global [%0], [%1], 16;" \
    :: "r"(dst), "l"(src))
#define CP_COMMIT() asm volatile("cp.async.commit_group;")
#define CP_WAIT(n)  asm volatile("cp.async.wait_group %0;" :: "n"(n))

__device__ __forceinline__ void ldsm4(uint32_t* d, uint32_t addr) {
    asm volatile("ldmatrix.sync.aligned.m8n8.x4.shared.b16 {%0,%1,%2,%3}, [%4];"
        : "=r"(d[0]), "=r"(d[1]), "=r"(d[2]), "=r"(d[3]) : "r"(addr));
}
__device__ __forceinline__ void mma16816(float* c, const uint32_t* a, uint32_t b0, uint32_t b1) {
    asm volatile("mma.sync.aligned.m16n8k16.row.col.f32.f16.f16.f32 "
        "{%0,%1,%2,%3}, {%4,%5,%6,%7}, {%8,%9}, {%0,%1,%2,%3};"
        : "+f"(c[0]), "+f"(c[1]), "+f"(c[2]), "+f"(c[3])
        : "r"(a[0]), "r"(a[1]), "r"(a[2]), "r"(a[3]), "r"(b0), "r"(b1));
}
__device__ __forceinline__ void splitH2(float x, float y, uint32_t& h2, uint32_t& l2) {
    __half2 h, l;
    h.x = __float2half_rn(x); l.x = __float2half_rn(x - __half2float(h.x));
    h.y = __float2half_rn(y); l.y = __float2half_rn(y - __half2float(h.y));
    h2 = *reinterpret_cast<uint32_t*>(&h);
    l2 = *reinterpret_cast<uint32_t*>(&l);
}

struct Ptrs { const float* bias[3]; void* out5[3]; };
struct WPtr { const float* w[5]; };

#define STGB 10240u     // 128 rows * 80 B per operand per stage
#define NSTG 5
#define SMEM_REQ (2u * NSTG * STGB)   // 102400

// ------------------------- GEMM (mma.sync f16->f32, NT) ---------------------
// C[r,c] = alpha * sum_k A[z][r][k] * B[z][c][k]
// EPI 0: fp32 out (strided)
// EPI 1: s1 A-cat3 out [z][512][1536] (h,h,l)
// EPI 2: proj3 (bias + head-remap cat3: z0=A-cat(q), z1/z2=B-cat(k,ck))
// EPI 3: proj2 (bias + fp32 out [8192][2048])
// EPI 4: ctx A-cat2 out [z][512][1024] (h,h)
template <int EPI>
__global__ __launch_bounds__(256, 2) void gemm_mma(
    const __half* __restrict__ A, long long sAz, int lda,
    const __half* __restrict__ B, long long sBz, int ldb,
    void* outp, float alpha, int K,
    long long sZ, long long sCb, long long sCh, int ldc, Ptrs pp)
{
    extern __shared__ char smraw[];
    const uint32_t baseA = (uint32_t)__cvta_generic_to_shared(smraw);
    const uint32_t baseB = baseA + NSTG * STGB;

    const int tid = threadIdx.x;
    const int lane = tid & 31, wid = tid >> 5;
    const int wm = wid >> 2, wn = wid & 3;          // 2x4 warps, warp tile 64x32
    const int m0 = blockIdx.y * 128, n0 = blockIdx.x * 128, z = blockIdx.z;

    const __half* Az = A + (size_t)z * sAz;
    const __half* Bz = B + (size_t)z * sBz;

    const int lr = tid >> 2, lq = tid & 3;
    const __half* gA0 = Az + (size_t)(m0 + lr) * lda + lq * 8;
    const __half* gA1 = Az + (size_t)(m0 + lr + 64) * lda + lq * 8;
    const __half* gB0 = Bz + (size_t)(n0 + lr) * ldb + lq * 8;
    const __half* gB1 = Bz + (size_t)(n0 + lr + 64) * ldb + lq * 8;

    const uint32_t dA0 = baseA + lr * 80 + lq * 16;
    const uint32_t dA1 = baseA + (lr + 64) * 80 + lq * 16;
    const uint32_t dB0 = baseB + lr * 80 + lq * 16;
    const uint32_t dB1 = baseB + (lr + 64) * 80 + lq * 16;

    const int lrow = (lane & 7) + ((lane >> 3) & 1) * 8;
    const int lchunk = lane >> 4;
    const uint32_t aAddr = (wm * 64 + lrow) * 80 + lchunk * 16;
    const uint32_t bAddr = (wn * 32 + lrow) * 80 + lchunk * 16;

    float acc[4][4][4];
#pragma unroll
    for (int i = 0; i < 4; i++)
#pragma unroll
        for (int j = 0; j < 4; j++) { acc[i][j][0]=0.f; acc[i][j][1]=0.f; acc[i][j][2]=0.f; acc[i][j][3]=0.f; }

#define LOADTILE(kt, st) do { \
    const size_t ko = (size_t)(kt) * 32; \
    const uint32_t so = (uint32_t)(st) * STGB; \
    CP16(dA0 + so, gA0 + ko); CP16(dA1 + so, gA1 + ko); \
    CP16(dB0 + so, gB0 + ko); CP16(dB1 + so, gB1 + ko); \
} while (0)

#define COMPUTE_CHUNK(st) do { \
    const uint32_t so = (uint32_t)(st) * STGB; \
    _Pragma("unroll") \
    for (int k16 = 0; k16 < 2; ++k16) { \
        const uint32_t kb = so + k16 * 32; \
        uint32_t a[4][4], bq[2][4]; \
        _Pragma("unroll") \
        for (int mi = 0; mi < 4; ++mi) ldsm4(a[mi], baseA + kb + aAddr + mi * (16*80)); \
        _Pragma("unroll") \
        for (int j = 0; j < 2; ++j) ldsm4(bq[j], baseB + kb + bAddr + j * (16*80)); \
        _Pragma("unroll") \
        for (int mi = 0; mi < 4; ++mi) \
            _Pragma("unroll") \
            for (int ni = 0; ni < 4; ++ni) \
                mma16816(acc[mi][ni], a[mi], bq[ni >> 1][ni & 1], bq[ni >> 1][2 + (ni & 1)]); \
    } \
} while (0)

    const int KT = K / 32;   // even for all our K (192,128,48,32)
    LOADTILE(0, 0); CP_COMMIT();
    LOADTILE(1, 1); CP_COMMIT();
    LOADTILE(2, 2); CP_COMMIT();

    int cs = 0, ls = 3;
    for (int kt = 0; kt < KT; kt += 2) {
        CP_WAIT(1);
        __syncthreads();
        const int ls2 = (ls + 1 == NSTG) ? 0 : ls + 1;
        if (kt + 3 < KT) { LOADTILE(kt + 3, ls); CP_COMMIT(); } else CP_COMMIT();
        if (kt + 4 < KT) { LOADTILE(kt + 4, ls2); CP_COMMIT(); } else CP_COMMIT();
        const int cs2 = (cs + 1 == NSTG) ? 0 : cs + 1;
        COMPUTE_CHUNK(cs);
        COMPUTE_CHUNK(cs2);
        cs = (cs2 + 1 == NSTG) ? 0 : cs2 + 1;
        ls = (ls2 + 1 == NSTG) ? 0 : ls2 + 1;
    }
#undef LOADTILE
#undef COMPUTE_CHUNK

    // ------------- epilogue -------------
    float* obase = nullptr;
    __half* cbase = nullptr;
    if (EPI == 0) obase = (float*)outp + (size_t)z * sZ + (size_t)(z >> 2) * sCb + (size_t)(z & 3) * sCh;
    if (EPI == 1) cbase = (__half*)outp + (size_t)z * SQ * K3A;
    if (EPI == 4) cbase = (__half*)outp + (size_t)z * SQ * K2A;
    const bool modeB = (z != 0);

#pragma unroll
    for (int mi = 0; mi < 4; ++mi)
#pragma unroll
        for (int ni = 0; ni < 4; ++ni) {
            const int r0 = m0 + wm * 64 + mi * 16 + (lane >> 2);
            const int c  = n0 + wn * 32 + ni * 8 + (lane & 3) * 2;
#pragma unroll
            for (int hh = 0; hh < 2; ++hh) {
                const int r = r0 + hh * 8;
                float v0 = acc[mi][ni][hh * 2], v1 = acc[mi][ni][hh * 2 + 1];
                if (EPI == 0) {
                    float2 f; f.x = v0 * alpha; f.y = v1 * alpha;
                    *(float2*)(obase + (size_t)r * ldc + c) = f;
                } else if (EPI == 1) {
                    uint32_t h2, l2; splitH2(v0, v1, h2, l2);
                    __half* o = cbase + (size_t)r * K3A + c;
                    *(uint32_t*)o = h2; *(uint32_t*)(o + 512) = h2; *(uint32_t*)(o + 1024) = l2;
                } else if (EPI == 4) {
                    uint32_t h2, l2; splitH2(v0, v1, h2, l2);
                    __half* o = cbase + (size_t)r * K2A + c;
                    *(uint32_t*)o = h2; *(uint32_t*)(o + 512) = h2;
                } else if (EPI == 3) {
                    v0 += pp.bias[z][c]; v1 += pp.bias[z][c + 1];
                    float2 f; f.x = v0; f.y = v1;
                    *(float2*)((float*)pp.out5[z] + (size_t)r * HID + c) = f;
                } else {   // EPI == 2
                    v0 += pp.bias[z][c]; v1 += pp.bias[z][c + 1];
                    uint32_t h2, l2; splitH2(v0, v1, h2, l2);
                    const int head = ((r >> 9) << 2) + (c >> 9);
                    __half* o = (__half*)pp.out5[z]
                        + ((size_t)(head * 512 + (r & 511))) * K3A + (c & 511);
                    *(uint32_t*)o = h2;
                    *(uint32_t*)(o + 512)  = modeB ? l2 : h2;
                    *(uint32_t*)(o + 1024) = modeB ? h2 : l2;
                }
            }
        }
}

// ------------------------- conversions -------------------------
// X -> x3 A-cat3 [h|h|l] (K=6144) and x2 A-cat2 [h|h] (K=4096)
__global__ void conv_x(const float* __restrict__ in, __half* __restrict__ x3,
                       __half* __restrict__ x2)
{
    const int r = blockIdx.y;
    const int k = (blockIdx.x * blockDim.x + threadIdx.x) * 2;
    float2 x = *(const float2*)(in + (size_t)r * HID + k);
    uint32_t h2, l2; splitH2(x.x, x.y, h2, l2);
    __half* o3 = x3 + (size_t)r * K3P + k;
    *(uint32_t*)o3              = h2;
    *(uint32_t*)(o3 + HID)      = h2;
    *(uint32_t*)(o3 + 2 * HID)  = l2;
    __half* o2 = x2 + (size_t)r * K2P + k;
    *(uint32_t*)o2              = h2;
    *(uint32_t*)(o2 + HID)      = h2;
}

// weights: z<3 (q,k,ck) -> w3 B-cat3 [h|l|h]; z>=3 (v,cv) -> w2 B-cat2 [h|l]
__global__ void conv_w(WPtr wp, __half* __restrict__ w3, __half* __restrict__ w2)
{
    const int w = blockIdx.z;
    const int r = blockIdx.y;
    const int k = (blockIdx.x * blockDim.x + threadIdx.x) * 2;
    float2 x = *(const float2*)(wp.w[w] + (size_t)r * HID + k);
    uint32_t h2, l2; splitH2(x.x, x.y, h2, l2);
    if (w < 3) {
        __half* o = w3 + ((size_t)w * HID + r) * K3P + k;
        *(uint32_t*)o             = h2;
        *(uint32_t*)(o + HID)     = l2;
        *(uint32_t*)(o + 2 * HID) = h2;
    } else {
        __half* o = w2 + ((size_t)(w - 3) * HID + r) * K2P + k;
        *(uint32_t*)o         = h2;
        *(uint32_t*)(o + HID) = l2;
    }
}

// fp32 [8192][2048] -> transposed B-cat2 [64][512(d)][1024]: [s]=h, [512+s]=l
__global__ void convT2(const float* __restrict__ in, __half* __restrict__ out)
{
    __shared__ float t[32][33];
    const int r0 = blockIdx.y * 32, c0 = blockIdx.x * 32;
    const int tx = threadIdx.x, ty = threadIdx.y;
#pragma unroll
    for (int i = ty; i < 32; i += 8)
        t[i][tx] = in[(size_t)(r0 + i) * HID + c0 + tx];
    __syncthreads();
#pragma unroll
    for (int i = ty; i < 32; i += 8) {
        float x = t[tx][i];
        const int s = (r0 + tx) & 511;
        const int head = ((r0 >> 9) << 2) + ((c0 + i) >> 9);
        const int dd = (c0 + i) & 511;
        __half h = __float2half_rn(x);
        __half l = __float2half_rn(x - __half2float(h));
        __half* o = out + ((size_t)(head * 512 + dd)) * K2A + s;
        o[0] = h; o[512] = l;
    }
}

// softmax rows of s2 -> P A-cat2 [row][1024]: [c]=h, [512+c]=h
__global__ __launch_bounds__(128) void softmax_h(const float* __restrict__ S,
                                                 __half* __restrict__ P)
{
    const size_t row = blockIdx.x;
    const int t = threadIdx.x;
    float4 v = ((const float4*)(S + row * SQ))[t];
    float m = fmaxf(fmaxf(v.x, v.y), fmaxf(v.z, v.w));
#pragma unroll
    for (int o = 16; o; o >>= 1) m = fmaxf(m, __shfl_xor_sync(0xffffffffu, m, o));
    __shared__ float rm[4];
    if ((t & 31) == 0) rm[t >> 5] = m;
    __syncthreads();
    m = fmaxf(fmaxf(rm[0], rm[1]), fmaxf(rm[2], rm[3]));
    v.x = expf(v.x - m); v.y = expf(v.y - m); v.z = expf(v.z - m); v.w = expf(v.w - m);
    float s = v.x + v.y + v.z + v.w;
#pragma unroll
    for (int o = 16; o; o >>= 1) s += __shfl_xor_sync(0xffffffffu, s, o);
    __shared__ float rs[4];
    if ((t & 31) == 0) rs[t >> 5] = s;
    __syncthreads();
    s = rs[0] + rs[1] + rs[2] + rs[3];
    const float inv = 1.0f / s;
    __half2 h0, h1;
    h0.x = __float2half_rn(v.x * inv); h0.y = __float2half_rn(v.y * inv);
    h1.x = __float2half_rn(v.z * inv); h1.y = __float2half_rn(v.w * inv);
    __half* o = P + row * K2A + t * 4;
    *(__half2*)o         = h0; *(__half2*)(o + 2)       = h1;
    *(__half2*)(o + 512) = h0; *(__half2*)(o + 514)     = h1;
}

// ------------------------- host -------------------------
extern "C" void kernel_launch(void* const* d_in, const int* in_sizes, int n_in,
                              void* d_out, int out_size)
{
    const float* X = (const float*)d_in[0];
    // order: q, k, ck (3-term) then v, cv (2-term)
    WPtr wp = {{(const float*)d_in[1], (const float*)d_in[3], (const float*)d_in[7],
                (const float*)d_in[5], (const float*)d_in[9]}};
    const float* bq  = (const float*)d_in[2];
    const float* bk  = (const float*)d_in[4];
    const float* bv  = (const float*)d_in[6];
    const float* bck = (const float*)d_in[8];
    const float* bcv = (const float*)d_in[10];

    void *x3, *x2, *w3, *w2, *ypv, *ypcv, *q3, *k3, *ck3, *vT2, *cvT2, *s13, *s2, *p2, *c2;
    cudaGetSymbolAddress(&x3, g_x3);     cudaGetSymbolAddress(&x2, g_x2);
    cudaGetSymbolAddress(&w3, g_w3);     cudaGetSymbolAddress(&w2, g_w2);
    cudaGetSymbolAddress(&ypv, g_ypv);   cudaGetSymbolAddress(&ypcv, g_ypcv);
    cudaGetSymbolAddress(&q3, g_q3);     cudaGetSymbolAddress(&k3, g_k3);
    cudaGetSymbolAddress(&ck3, g_ck3);   cudaGetSymbolAddress(&vT2, g_vT2);
    cudaGetSymbolAddress(&cvT2, g_cvT2); cudaGetSymbolAddress(&s13, g_s13);
    cudaGetSymbolAddress(&s2, g_s2);     cudaGetSymbolAddress(&p2, g_p2);
    cudaGetSymbolAddress(&c2, g_c2);

    Ptrs pp3;   // proj3: z0=q(A-cat), z1=k, z2=ck (B-cat)
    pp3.bias[0] = bq;  pp3.out5[0] = q3;
    pp3.bias[1] = bk;  pp3.out5[1] = k3;
    pp3.bias[2] = bck; pp3.out5[2] = ck3;
    Ptrs pp2;   // proj2: z0=v, z1=cv -> fp32
    pp2.bias[0] = bv;  pp2.out5[0] = ypv;
    pp2.bias[1] = bcv; pp2.out5[1] = ypcv;
    pp2.bias[2] = bv;  pp2.out5[2] = ypv;
    Ptrs pz = pp3;

    static bool attr_done = false;
    if (!attr_done) {
        cudaFuncSetAttribute(gemm_mma<0>, cudaFuncAttributeMaxDynamicSharedMemorySize, SMEM_REQ);
        cudaFuncSetAttribute(gemm_mma<1>, cudaFuncAttributeMaxDynamicSharedMemorySize, SMEM_REQ);
        cudaFuncSetAttribute(gemm_mma<2>, cudaFuncAttributeMaxDynamicSharedMemorySize, SMEM_REQ);
        cudaFuncSetAttribute(gemm_mma<3>, cudaFuncAttributeMaxDynamicSharedMemorySize, SMEM_REQ);
        cudaFuncSetAttribute(gemm_mma<4>, cudaFuncAttributeMaxDynamicSharedMemorySize, SMEM_REQ);
        attr_done = true;
    }

    const long long s3 = (long long)SQ * K3A;
    const long long s2a = (long long)SQ * K2A;
    dim3 ga(SQ / 128, SQ / 128, NZ);

    // 0: X conversions (A-cat3 + A-cat2)
    conv_x<<<dim3(8, MR), 128>>>(X, (__half*)x3, (__half*)x2);
    // 1: weight conversions
    conv_w<<<dim3(8, HID, 5), 128>>>(wp, (__half*)w3, (__half*)w2);
    // 2: proj3 (q,k,ck): K=6144 -> head-remapped cat3
    gemm_mma<2><<<dim3(HID / 128, MR / 128, 3), 256, SMEM_REQ>>>(
        (const __half*)x3, 0LL, K3P, (const __half*)w3, (long long)HID * K3P, K3P,
        nullptr, 1.0f, K3P, 0, 0, 0, 0, pp3);
    // 3: proj2 (v,cv): K=4096 -> fp32 + bias
    gemm_mma<3><<<dim3(HID / 128, MR / 128, 2), 256, SMEM_REQ>>>(
        (const __half*)x2, 0LL, K2P, (const __half*)w2, (long long)HID * K2P, K2P,
        nullptr, 1.0f, K2P, 0, 0, 0, 0, pp2);
    // 4,5: transpose B-cat2 for V, CV
    convT2<<<dim3(HID / 32, MR / 32), dim3(32, 8)>>>((const float*)ypv, (__half*)vT2);
    convT2<<<dim3(HID / 32, MR / 32), dim3(32, 8)>>>((const float*)ypcv, (__half*)cvT2);
    // 6: s1 = q @ k^T (3-term, K=1536) -> s1 A-cat3
    gemm_mma<1><<<ga, 256, SMEM_REQ>>>(
        (const __half*)q3, s3, K3A, (const __half*)k3, s3, K3A,
        s13, 1.0f, K3A, 0, 0, 0, 0, pz);
    // 7: s2 = (s1 @ ck^T) * SCALE (3-term) -> fp32
    gemm_mma<0><<<ga, 256, SMEM_REQ>>>(
        (const __half*)s13, s3, K3A, (const __half*)ck3, s3, K3A,
        s2, SCALE_F, K3A, (long long)SQ * SQ, 0, 0, SQ, pz);
    // 8: softmax -> P A-cat2
    softmax_h<<<NZ * SQ, 128>>>((const float*)s2, (__half*)p2);
    // 9: ctx = P @ V (2-term, K=1024) -> ctx A-cat2
    gemm_mma<4><<<ga, 256, SMEM_REQ>>>(
        (const __half*)p2, s2a, K2A, (const __half*)vT2, s2a, K2A,
        c2, 1.0f, K2A, 0, 0, 0, 0, pz);
    // 10: out = ctx @ CV (2-term, K=1024) -> d_out [b][s][h*512+e]
    gemm_mma<0><<<ga, 256, SMEM_REQ>>>(
        (const __half*)c2, s2a, K2A, (const __half*)cvT2, s2a, K2A,
        d_out, 1.0f, K2A, 0, (long long)SQ * HID, 512, HID, pz);
}

// round 12
// speedup vs baseline: 1.3252x; 1.0380x over previous
#include <cuda_runtime.h>
#include <cuda_fp16.h>
#include <cstdint>
#include <cstddef>
#include <math.h>

#define SQ  512
#define HID 2048
#define NZ  64
#define MR  8192
#define K3A 1536
#define K2A 1024
#define K3P 6144
#define K2P 4096

static const float SCALE_F = 0.04419417382415922f;

// ------------------------- scratch -------------------------
__device__ __align__(1024) __half g_x3  [(size_t)MR*K3P];      // [h|h|l]; first 4096 cols = [h|h]
__device__ __align__(1024) __half g_w3  [(size_t)3*HID*K3P];
__device__ __align__(1024) __half g_w2  [(size_t)2*HID*K2P];
__device__ __align__(1024) float  g_ypv [(size_t)MR*HID];
__device__ __align__(1024) float  g_ypcv[(size_t)MR*HID];
__device__ __align__(1024) __half g_q3  [(size_t)NZ*SQ*K3A];
__device__ __align__(1024) __half g_k3  [(size_t)NZ*SQ*K3A];
__device__ __align__(1024) __half g_ck3 [(size_t)NZ*SQ*K3A];
__device__ __align__(1024) __half g_vT2 [(size_t)NZ*SQ*K2A];
__device__ __align__(1024) __half g_cvT2[(size_t)NZ*SQ*K2A];
__device__ __align__(1024) __half g_s13 [(size_t)NZ*SQ*K3A];
__device__ __align__(1024) float  g_s2  [(size_t)NZ*SQ*SQ];
__device__ __align__(1024) __half g_p2  [(size_t)NZ*SQ*K2A];
__device__ __align__(1024) __half g_c2  [(size_t)NZ*SQ*K2A];

// ------------------------- helpers -------------------------
#define CP16(dst, src) asm volatile("cp.async.cg.shared.global [%0], [%1], 16;" \
    :: "r"(dst), "l"(src))
#define CP_COMMIT() asm volatile("cp.async.commit_group;")
#define CP_WAIT(n)  asm volatile("cp.async.wait_group %0;" :: "n"(n))

__device__ __forceinline__ void ldsm4(uint32_t* d, uint32_t addr) {
    asm volatile("ldmatrix.sync.aligned.m8n8.x4.shared.b16 {%0,%1,%2,%3}, [%4];"
        : "=r"(d[0]), "=r"(d[1]), "=r"(d[2]), "=r"(d[3]) : "r"(addr));
}
__device__ __forceinline__ void mma16816(float* c, const uint32_t* a, uint32_t b0, uint32_t b1) {
    asm volatile("mma.sync.aligned.m16n8k16.row.col.f32.f16.f16.f32 "
        "{%0,%1,%2,%3}, {%4,%5,%6,%7}, {%8,%9}, {%0,%1,%2,%3};"
        : "+f"(c[0]), "+f"(c[1]), "+f"(c[2]), "+f"(c[3])
        : "r"(a[0]), "r"(a[1]), "r"(a[2]), "r"(a[3]), "r"(b0), "r"(b1));
}
__device__ __forceinline__ void splitH2(float x, float y, uint32_t& h2, uint32_t& l2) {
    __half2 h, l;
    h.x = __float2half_rn(x); l.x = __float2half_rn(x - __half2float(h.x));
    h.y = __float2half_rn(y); l.y = __float2half_rn(y - __half2float(h.y));
    h2 = *reinterpret_cast<uint32_t*>(&h);
    l2 = *reinterpret_cast<uint32_t*>(&l);
}

struct Ptrs { const float* bias[3]; void* out5[3]; };
struct WPtr { const float* w[5]; };

#define STGB 10240u
#define NSTG 5
#define SMEM_REQ (2u * NSTG * STGB)

// ------------------------- GEMM (mma.sync f16->f32, NT) ---------------------
// EPI 0: fp32 out; EPI 1: s1 A-cat3; EPI 2: proj3 head-remap cat3;
// EPI 3: proj2 fp32+bias; EPI 4: ctx A-cat2
template <int EPI>
__global__ __launch_bounds__(256, 2) void gemm_mma(
    const __half* __restrict__ A, long long sAz, int lda,
    const __half* __restrict__ B, long long sBz, int ldb,
    void* outp, float alpha, int K,
    long long sZ, long long sCb, long long sCh, int ldc, Ptrs pp)
{
    extern __shared__ char smraw[];
    const uint32_t baseA = (uint32_t)__cvta_generic_to_shared(smraw);
    const uint32_t baseB = baseA + NSTG * STGB;

    const int tid = threadIdx.x;
    const int lane = tid & 31, wid = tid >> 5;
    const int wm = wid >> 2, wn = wid & 3;
    const int m0 = blockIdx.y * 128, n0 = blockIdx.x * 128, z = blockIdx.z;

    const __half* Az = A + (size_t)z * sAz;
    const __half* Bz = B + (size_t)z * sBz;

    const int lr = tid >> 2, lq = tid & 3;
    const __half* gA0 = Az + (size_t)(m0 + lr) * lda + lq * 8;
    const __half* gA1 = Az + (size_t)(m0 + lr + 64) * lda + lq * 8;
    const __half* gB0 = Bz + (size_t)(n0 + lr) * ldb + lq * 8;
    const __half* gB1 = Bz + (size_t)(n0 + lr + 64) * ldb + lq * 8;

    const uint32_t dA0 = baseA + lr * 80 + lq * 16;
    const uint32_t dA1 = baseA + (lr + 64) * 80 + lq * 16;
    const uint32_t dB0 = baseB + lr * 80 + lq * 16;
    const uint32_t dB1 = baseB + (lr + 64) * 80 + lq * 16;

    const int lrow = (lane & 7) + ((lane >> 3) & 1) * 8;
    const int lchunk = lane >> 4;
    const uint32_t aAddr = (wm * 64 + lrow) * 80 + lchunk * 16;
    const uint32_t bAddr = (wn * 32 + lrow) * 80 + lchunk * 16;

    float acc[4][4][4];
#pragma unroll
    for (int i = 0; i < 4; i++)
#pragma unroll
        for (int j = 0; j < 4; j++) { acc[i][j][0]=0.f; acc[i][j][1]=0.f; acc[i][j][2]=0.f; acc[i][j][3]=0.f; }

#define LOADTILE(kt, st) do { \
    const size_t ko = (size_t)(kt) * 32; \
    const uint32_t so = (uint32_t)(st) * STGB; \
    CP16(dA0 + so, gA0 + ko); CP16(dA1 + so, gA1 + ko); \
    CP16(dB0 + so, gB0 + ko); CP16(dB1 + so, gB1 + ko); \
} while (0)

#define COMPUTE_CHUNK(st) do { \
    const uint32_t so = (uint32_t)(st) * STGB; \
    _Pragma("unroll") \
    for (int k16 = 0; k16 < 2; ++k16) { \
        const uint32_t kb = so + k16 * 32; \
        uint32_t a[4][4], bq[2][4]; \
        _Pragma("unroll") \
        for (int mi = 0; mi < 4; ++mi) ldsm4(a[mi], baseA + kb + aAddr + mi * (16*80)); \
        _Pragma("unroll") \
        for (int j = 0; j < 2; ++j) ldsm4(bq[j], baseB + kb + bAddr + j * (16*80)); \
        _Pragma("unroll") \
        for (int mi = 0; mi < 4; ++mi) \
            _Pragma("unroll") \
            for (int ni = 0; ni < 4; ++ni) \
                mma16816(acc[mi][ni], a[mi], bq[ni >> 1][ni & 1], bq[ni >> 1][2 + (ni & 1)]); \
    } \
} while (0)

    const int KT = K / 32;
    LOADTILE(0, 0); CP_COMMIT();
    LOADTILE(1, 1); CP_COMMIT();
    LOADTILE(2, 2); CP_COMMIT();

    int cs = 0, ls = 3;
    for (int kt = 0; kt < KT; kt += 2) {
        CP_WAIT(1);
        __syncthreads();
        const int ls2 = (ls + 1 == NSTG) ? 0 : ls + 1;
        if (kt + 3 < KT) { LOADTILE(kt + 3, ls); CP_COMMIT(); } else CP_COMMIT();
        if (kt + 4 < KT) { LOADTILE(kt + 4, ls2); CP_COMMIT(); } else CP_COMMIT();
        const int cs2 = (cs + 1 == NSTG) ? 0 : cs + 1;
        COMPUTE_CHUNK(cs);
        COMPUTE_CHUNK(cs2);
        cs = (cs2 + 1 == NSTG) ? 0 : cs2 + 1;
        ls = (ls2 + 1 == NSTG) ? 0 : ls2 + 1;
    }
#undef LOADTILE
#undef COMPUTE_CHUNK

    float* obase = nullptr;
    __half* cbase = nullptr;
    if (EPI == 0) obase = (float*)outp + (size_t)z * sZ + (size_t)(z >> 2) * sCb + (size_t)(z & 3) * sCh;
    if (EPI == 1) cbase = (__half*)outp + (size_t)z * SQ * K3A;
    if (EPI == 4) cbase = (__half*)outp + (size_t)z * SQ * K2A;
    const bool modeB = (z != 0);

#pragma unroll
    for (int mi = 0; mi < 4; ++mi)
#pragma unroll
        for (int ni = 0; ni < 4; ++ni) {
            const int r0 = m0 + wm * 64 + mi * 16 + (lane >> 2);
            const int c  = n0 + wn * 32 + ni * 8 + (lane & 3) * 2;
#pragma unroll
            for (int hh = 0; hh < 2; ++hh) {
                const int r = r0 + hh * 8;
                float v0 = acc[mi][ni][hh * 2], v1 = acc[mi][ni][hh * 2 + 1];
                if (EPI == 0) {
                    float2 f; f.x = v0 * alpha; f.y = v1 * alpha;
                    *(float2*)(obase + (size_t)r * ldc + c) = f;
                } else if (EPI == 1) {
                    uint32_t h2, l2; splitH2(v0, v1, h2, l2);
                    __half* o = cbase + (size_t)r * K3A + c;
                    *(uint32_t*)o = h2; *(uint32_t*)(o + 512) = h2; *(uint32_t*)(o + 1024) = l2;
                } else if (EPI == 4) {
                    uint32_t h2, l2; splitH2(v0, v1, h2, l2);
                    __half* o = cbase + (size_t)r * K2A + c;
                    *(uint32_t*)o = h2; *(uint32_t*)(o + 512) = h2;
                } else if (EPI == 3) {
                    v0 += pp.bias[z][c]; v1 += pp.bias[z][c + 1];
                    float2 f; f.x = v0; f.y = v1;
                    *(float2*)((float*)pp.out5[z] + (size_t)r * HID + c) = f;
                } else {   // EPI == 2
                    v0 += pp.bias[z][c]; v1 += pp.bias[z][c + 1];
                    uint32_t h2, l2; splitH2(v0, v1, h2, l2);
                    const int head = ((r >> 9) << 2) + (c >> 9);
                    __half* o = (__half*)pp.out5[z]
                        + ((size_t)(head * 512 + (r & 511))) * K3A + (c & 511);
                    *(uint32_t*)o = h2;
                    *(uint32_t*)(o + 512)  = modeB ? l2 : h2;
                    *(uint32_t*)(o + 1024) = modeB ? h2 : l2;
                }
            }
        }
}

// ------------------------- conversions -------------------------
// X -> x3 A-cat3 [h|h|l] (first 4096 cols double as A-cat2)
__global__ void conv_x(const float* __restrict__ in, __half* __restrict__ x3)
{
    const int r = blockIdx.y;
    const int k = (blockIdx.x * blockDim.x + threadIdx.x) * 2;
    float2 x = *(const float2*)(in + (size_t)r * HID + k);
    uint32_t h2, l2; splitH2(x.x, x.y, h2, l2);
    __half* o3 = x3 + (size_t)r * K3P + k;
    *(uint32_t*)o3              = h2;
    *(uint32_t*)(o3 + HID)      = h2;
    *(uint32_t*)(o3 + 2 * HID)  = l2;
}

__global__ void conv_w(WPtr wp, __half* __restrict__ w3, __half* __restrict__ w2)
{
    const int w = blockIdx.z;
    const int r = blockIdx.y;
    const int k = (blockIdx.x * blockDim.x + threadIdx.x) * 2;
    float2 x = *(const float2*)(wp.w[w] + (size_t)r * HID + k);
    uint32_t h2, l2; splitH2(x.x, x.y, h2, l2);
    if (w < 3) {
        __half* o = w3 + ((size_t)w * HID + r) * K3P + k;
        *(uint32_t*)o             = h2;
        *(uint32_t*)(o + HID)     = l2;
        *(uint32_t*)(o + 2 * HID) = h2;
    } else {
        __half* o = w2 + ((size_t)(w - 3) * HID + r) * K2P + k;
        *(uint32_t*)o         = h2;
        *(uint32_t*)(o + HID) = l2;
    }
}

__global__ void convT2(const float* __restrict__ in, __half* __restrict__ out)
{
    __shared__ float t[32][33];
    const int r0 = blockIdx.y * 32, c0 = blockIdx.x * 32;
    const int tx = threadIdx.x, ty = threadIdx.y;
#pragma unroll
    for (int i = ty; i < 32; i += 8)
        t[i][tx] = in[(size_t)(r0 + i) * HID + c0 + tx];
    __syncthreads();
#pragma unroll
    for (int i = ty; i < 32; i += 8) {
        float x = t[tx][i];
        const int s = (r0 + tx) & 511;
        const int head = ((r0 >> 9) << 2) + ((c0 + i) >> 9);
        const int dd = (c0 + i) & 511;
        __half h = __float2half_rn(x);
        __half l = __float2half_rn(x - __half2float(h));
        __half* o = out + ((size_t)(head * 512 + dd)) * K2A + s;
        o[0] = h; o[512] = l;
    }
}

__global__ __launch_bounds__(128) void softmax_h(const float* __restrict__ S,
                                                 __half* __restrict__ P)
{
    const size_t row = blockIdx.x;
    const int t = threadIdx.x;
    float4 v = ((const float4*)(S + row * SQ))[t];
    float m = fmaxf(fmaxf(v.x, v.y), fmaxf(v.z, v.w));
#pragma unroll
    for (int o = 16; o; o >>= 1) m = fmaxf(m, __shfl_xor_sync(0xffffffffu, m, o));
    __shared__ float rm[4];
    if ((t & 31) == 0) rm[t >> 5] = m;
    __syncthreads();
    m = fmaxf(fmaxf(rm[0], rm[1]), fmaxf(rm[2], rm[3]));
    v.x = expf(v.x - m); v.y = expf(v.y - m); v.z = expf(v.z - m); v.w = expf(v.w - m);
    float s = v.x + v.y + v.z + v.w;
#pragma unroll
    for (int o = 16; o; o >>= 1) s += __shfl_xor_sync(0xffffffffu, s, o);
    __shared__ float rs[4];
    if ((t & 31) == 0) rs[t >> 5] = s;
    __syncthreads();
    s = rs[0] + rs[1] + rs[2] + rs[3];
    const float inv = 1.0f / s;
    __half2 h0, h1;
    h0.x = __float2half_rn(v.x * inv); h0.y = __float2half_rn(v.y * inv);
    h1.x = __float2half_rn(v.z * inv); h1.y = __float2half_rn(v.w * inv);
    __half* o = P + row * K2A + t * 4;
    *(__half2*)o         = h0; *(__half2*)(o + 2)   = h1;
    *(__half2*)(o + 512) = h0; *(__half2*)(o + 514) = h1;
}

// ------------------------- host -------------------------
extern "C" void kernel_launch(void* const* d_in, const int* in_sizes, int n_in,
                              void* d_out, int out_size)
{
    const float* X = (const float*)d_in[0];
    WPtr wp = {{(const float*)d_in[1], (const float*)d_in[3], (const float*)d_in[7],
                (const float*)d_in[5], (const float*)d_in[9]}};
    const float* bq  = (const float*)d_in[2];
    const float* bk  = (const float*)d_in[4];
    const float* bv  = (const float*)d_in[6];
    const float* bck = (const float*)d_in[8];
    const float* bcv = (const float*)d_in[10];

    void *x3, *w3, *w2, *ypv, *ypcv, *q3, *k3, *ck3, *vT2, *cvT2, *s13, *s2, *p2, *c2;
    cudaGetSymbolAddress(&x3, g_x3);
    cudaGetSymbolAddress(&w3, g_w3);     cudaGetSymbolAddress(&w2, g_w2);
    cudaGetSymbolAddress(&ypv, g_ypv);   cudaGetSymbolAddress(&ypcv, g_ypcv);
    cudaGetSymbolAddress(&q3, g_q3);     cudaGetSymbolAddress(&k3, g_k3);
    cudaGetSymbolAddress(&ck3, g_ck3);   cudaGetSymbolAddress(&vT2, g_vT2);
    cudaGetSymbolAddress(&cvT2, g_cvT2); cudaGetSymbolAddress(&s13, g_s13);
    cudaGetSymbolAddress(&s2, g_s2);     cudaGetSymbolAddress(&p2, g_p2);
    cudaGetSymbolAddress(&c2, g_c2);

    Ptrs pp3;
    pp3.bias[0] = bq;  pp3.out5[0] = q3;
    pp3.bias[1] = bk;  pp3.out5[1] = k3;
    pp3.bias[2] = bck; pp3.out5[2] = ck3;
    Ptrs pp2;
    pp2.bias[0] = bv;  pp2.out5[0] = ypv;
    pp2.bias[1] = bcv; pp2.out5[1] = ypcv;
    pp2.bias[2] = bv;  pp2.out5[2] = ypv;
    Ptrs pz = pp3;

    static bool init_done = false;
    static cudaStream_t sB;
    static cudaEvent_t evRoot, evB;
    if (!init_done) {
        cudaFuncSetAttribute(gemm_mma<0>, cudaFuncAttributeMaxDynamicSharedMemorySize, SMEM_REQ);
        cudaFuncSetAttribute(gemm_mma<1>, cudaFuncAttributeMaxDynamicSharedMemorySize, SMEM_REQ);
        cudaFuncSetAttribute(gemm_mma<2>, cudaFuncAttributeMaxDynamicSharedMemorySize, SMEM_REQ);
        cudaFuncSetAttribute(gemm_mma<3>, cudaFuncAttributeMaxDynamicSharedMemorySize, SMEM_REQ);
        cudaFuncSetAttribute(gemm_mma<4>, cudaFuncAttributeMaxDynamicSharedMemorySize, SMEM_REQ);
        cudaStreamCreateWithFlags(&sB, cudaStreamNonBlocking);
        cudaEventCreateWithFlags(&evRoot, cudaEventDisableTiming);
        cudaEventCreateWithFlags(&evB, cudaEventDisableTiming);
        init_done = true;
    }

    const long long s3 = (long long)SQ * K3A;
    const long long s2a = (long long)SQ * K2A;
    dim3 ga(SQ / 128, SQ / 128, NZ);

    // roots (default stream)
    conv_x<<<dim3(8, MR), 128>>>(X, (__half*)x3);
    conv_w<<<dim3(8, HID, 5), 128>>>(wp, (__half*)w3, (__half*)w2);
    cudaEventRecord(evRoot, 0);

    // branch B: proj2 (v,cv) + transposes  (A = x3 prefix [h|h], lda=K3P)
    cudaStreamWaitEvent(sB, evRoot, 0);
    gemm_mma<3><<<dim3(HID / 128, MR / 128, 2), 256, SMEM_REQ, sB>>>(
        (const __half*)x3, 0LL, K3P, (const __half*)w2, (long long)HID * K2P, K2P,
        nullptr, 1.0f, K2P, 0, 0, 0, 0, pp2);
    convT2<<<dim3(HID / 32, MR / 32), dim3(32, 8), 0, sB>>>((const float*)ypv, (__half*)vT2);
    convT2<<<dim3(HID / 32, MR / 32), dim3(32, 8), 0, sB>>>((const float*)ypcv, (__half*)cvT2);
    cudaEventRecord(evB, sB);

    // branch A (default stream): proj3 -> s1 -> s2 -> softmax
    gemm_mma<2><<<dim3(HID / 128, MR / 128, 3), 256, SMEM_REQ>>>(
        (const __half*)x3, 0LL, K3P, (const __half*)w3, (long long)HID * K3P, K3P,
        nullptr, 1.0f, K3P, 0, 0, 0, 0, pp3);
    gemm_mma<1><<<ga, 256, SMEM_REQ>>>(
        (const __half*)q3, s3, K3A, (const __half*)k3, s3, K3A,
        s13, 1.0f, K3A, 0, 0, 0, 0, pz);
    gemm_mma<0><<<ga, 256, SMEM_REQ>>>(
        (const __half*)s13, s3, K3A, (const __half*)ck3, s3, K3A,
        s2, SCALE_F, K3A, (long long)SQ * SQ, 0, 0, SQ, pz);
    softmax_h<<<NZ * SQ, 128>>>((const float*)s2, (__half*)p2);

    // join: PV and out need branch B
    cudaStreamWaitEvent(0, evB, 0);
    gemm_mma<4><<<ga, 256, SMEM_REQ>>>(
        (const __half*)p2, s2a, K2A, (const __half*)vT2, s2a, K2A,
        c2, 1.0f, K2A, 0, 0, 0, 0, pz);
    gemm_mma<0><<<ga, 256, SMEM_REQ>>>(
        (const __half*)c2, s2a, K2A, (const __half*)cvT2, s2a, K2A,
        d_out, 1.0f, K2A, 0, (long long)SQ * HID, 512, HID, pz);
}

// round 13
// speedup vs baseline: 1.3335x; 1.0063x over previous
#include <cuda_runtime.h>
#include <cuda_fp16.h>
#include <cstdint>
#include <cstddef>
#include <math.h>

#define SQ  512
#define HID 2048
#define NZ  64
#define MR  8192
#define K3A 1536
#define K2A 1024
#define K3P 6144
#define K2P 4096

static const float SCALE_F = 0.04419417382415922f;

// ------------------------- scratch -------------------------
__device__ __align__(1024) __half g_x3  [(size_t)MR*K3P];   // [h|h|l]; first 4096 cols = [h|h]
__device__ __align__(1024) __half g_w3  [(size_t)3*HID*K3P];
__device__ __align__(1024) __half g_w2  [(size_t)2*HID*K2P];
__device__ __align__(1024) float  g_ypv [(size_t)MR*HID];
__device__ __align__(1024) float  g_ypcv[(size_t)MR*HID];
__device__ __align__(1024) __half g_q3  [(size_t)NZ*SQ*K3A];
__device__ __align__(1024) __half g_k3  [(size_t)NZ*SQ*K3A];
__device__ __align__(1024) __half g_ck3 [(size_t)NZ*SQ*K3A];
__device__ __align__(1024) __half g_vT2 [(size_t)NZ*SQ*K2A];
__device__ __align__(1024) __half g_cvT2[(size_t)NZ*SQ*K2A];
__device__ __align__(1024) __half g_s13 [(size_t)NZ*SQ*K3A];
__device__ __align__(1024) float  g_s2  [(size_t)NZ*SQ*SQ];
__device__ __align__(1024) __half g_p2  [(size_t)NZ*SQ*K2A];
__device__ __align__(1024) __half g_c2  [(size_t)NZ*SQ*K2A];

// ------------------------- helpers -------------------------
#define CP16(dst, src) asm volatile("cp.async.cg.shared.global [%0], [%1], 16;" \
    :: "r"(dst), "l"(src))
#define CP_COMMIT() asm volatile("cp.async.commit_group;")
#define CP_WAIT(n)  asm volatile("cp.async.wait_group %0;" :: "n"(n))

__device__ __forceinline__ void ldsm4(uint32_t* d, uint32_t addr) {
    asm volatile("ldmatrix.sync.aligned.m8n8.x4.shared.b16 {%0,%1,%2,%3}, [%4];"
        : "=r"(d[0]), "=r"(d[1]), "=r"(d[2]), "=r"(d[3]) : "r"(addr));
}
__device__ __forceinline__ void mma16816(float* c, const uint32_t* a, uint32_t b0, uint32_t b1) {
    asm volatile("mma.sync.aligned.m16n8k16.row.col.f32.f16.f16.f32 "
        "{%0,%1,%2,%3}, {%4,%5,%6,%7}, {%8,%9}, {%0,%1,%2,%3};"
        : "+f"(c[0]), "+f"(c[1]), "+f"(c[2]), "+f"(c[3])
        : "r"(a[0]), "r"(a[1]), "r"(a[2]), "r"(a[3]), "r"(b0), "r"(b1));
}
__device__ __forceinline__ void splitH2(float x, float y, uint32_t& h2, uint32_t& l2) {
    __half2 h, l;
    h.x = __float2half_rn(x); l.x = __float2half_rn(x - __half2float(h.x));
    h.y = __float2half_rn(y); l.y = __float2half_rn(y - __half2float(h.y));
    h2 = *reinterpret_cast<uint32_t*>(&h);
    l2 = *reinterpret_cast<uint32_t*>(&l);
}

struct Ptrs { const float* bias[3]; void* out5[3]; };
struct WPtr { const float* w[5]; };

#define STGB 10240u
#define NSTG 5
#define SMEM_REQ (2u * NSTG * STGB)

// ------------------------- GEMM (mma.sync f16->f32, NT) ---------------------
// EPI 0: fp32 out; EPI 1: s1 A-cat3; EPI 2: proj3 head-remap cat3;
// EPI 3: proj2 fp32+bias; EPI 4: ctx A-cat2
template <int EPI>
__global__ __launch_bounds__(256, 2) void gemm_mma(
    const __half* __restrict__ A, long long sAz, int lda,
    const __half* __restrict__ B, long long sBz, int ldb,
    void* outp, float alpha, int K,
    long long sZ, long long sCb, long long sCh, int ldc, Ptrs pp)
{
    extern __shared__ char smraw[];
    const uint32_t baseA = (uint32_t)__cvta_generic_to_shared(smraw);
    const uint32_t baseB = baseA + NSTG * STGB;

    const int tid = threadIdx.x;
    const int lane = tid & 31, wid = tid >> 5;
    const int wm = wid >> 2, wn = wid & 3;
    const int m0 = blockIdx.y * 128, n0 = blockIdx.x * 128, z = blockIdx.z;

    const __half* Az = A + (size_t)z * sAz;
    const __half* Bz = B + (size_t)z * sBz;

    const int lr = tid >> 2, lq = tid & 3;
    const __half* gA0 = Az + (size_t)(m0 + lr) * lda + lq * 8;
    const __half* gA1 = Az + (size_t)(m0 + lr + 64) * lda + lq * 8;
    const __half* gB0 = Bz + (size_t)(n0 + lr) * ldb + lq * 8;
    const __half* gB1 = Bz + (size_t)(n0 + lr + 64) * ldb + lq * 8;

    const uint32_t dA0 = baseA + lr * 80 + lq * 16;
    const uint32_t dA1 = baseA + (lr + 64) * 80 + lq * 16;
    const uint32_t dB0 = baseB + lr * 80 + lq * 16;
    const uint32_t dB1 = baseB + (lr + 64) * 80 + lq * 16;

    const int lrow = (lane & 7) + ((lane >> 3) & 1) * 8;
    const int lchunk = lane >> 4;
    const uint32_t aAddr = (wm * 64 + lrow) * 80 + lchunk * 16;
    const uint32_t bAddr = (wn * 32 + lrow) * 80 + lchunk * 16;

    float acc[4][4][4];
#pragma unroll
    for (int i = 0; i < 4; i++)
#pragma unroll
        for (int j = 0; j < 4; j++) { acc[i][j][0]=0.f; acc[i][j][1]=0.f; acc[i][j][2]=0.f; acc[i][j][3]=0.f; }

#define LOADTILE(kt, st) do { \
    const size_t ko = (size_t)(kt) * 32; \
    const uint32_t so = (uint32_t)(st) * STGB; \
    CP16(dA0 + so, gA0 + ko); CP16(dA1 + so, gA1 + ko); \
    CP16(dB0 + so, gB0 + ko); CP16(dB1 + so, gB1 + ko); \
} while (0)

#define COMPUTE_CHUNK(st) do { \
    const uint32_t so = (uint32_t)(st) * STGB; \
    _Pragma("unroll") \
    for (int k16 = 0; k16 < 2; ++k16) { \
        const uint32_t kb = so + k16 * 32; \
        uint32_t a[4][4], bq[2][4]; \
        _Pragma("unroll") \
        for (int mi = 0; mi < 4; ++mi) ldsm4(a[mi], baseA + kb + aAddr + mi * (16*80)); \
        _Pragma("unroll") \
        for (int j = 0; j < 2; ++j) ldsm4(bq[j], baseB + kb + bAddr + j * (16*80)); \
        _Pragma("unroll") \
        for (int mi = 0; mi < 4; ++mi) \
            _Pragma("unroll") \
            for (int ni = 0; ni < 4; ++ni) \
                mma16816(acc[mi][ni], a[mi], bq[ni >> 1][ni & 1], bq[ni >> 1][2 + (ni & 1)]); \
    } \
} while (0)

    const int KT = K / 32;
    LOADTILE(0, 0); CP_COMMIT();
    LOADTILE(1, 1); CP_COMMIT();
    LOADTILE(2, 2); CP_COMMIT();

    int cs = 0, ls = 3;
    for (int kt = 0; kt < KT; kt += 2) {
        CP_WAIT(1);
        __syncthreads();
        const int ls2 = (ls + 1 == NSTG) ? 0 : ls + 1;
        if (kt + 3 < KT) { LOADTILE(kt + 3, ls); CP_COMMIT(); } else CP_COMMIT();
        if (kt + 4 < KT) { LOADTILE(kt + 4, ls2); CP_COMMIT(); } else CP_COMMIT();
        const int cs2 = (cs + 1 == NSTG) ? 0 : cs + 1;
        COMPUTE_CHUNK(cs);
        COMPUTE_CHUNK(cs2);
        cs = (cs2 + 1 == NSTG) ? 0 : cs2 + 1;
        ls = (ls2 + 1 == NSTG) ? 0 : ls2 + 1;
    }
#undef LOADTILE
#undef COMPUTE_CHUNK

    float* obase = nullptr;
    __half* cbase = nullptr;
    if (EPI == 0) obase = (float*)outp + (size_t)z * sZ + (size_t)(z >> 2) * sCb + (size_t)(z & 3) * sCh;
    if (EPI == 1) cbase = (__half*)outp + (size_t)z * SQ * K3A;
    if (EPI == 4) cbase = (__half*)outp + (size_t)z * SQ * K2A;
    const bool modeB = (z != 0);

#pragma unroll
    for (int mi = 0; mi < 4; ++mi)
#pragma unroll
        for (int ni = 0; ni < 4; ++ni) {
            const int r0 = m0 + wm * 64 + mi * 16 + (lane >> 2);
            const int c  = n0 + wn * 32 + ni * 8 + (lane & 3) * 2;
#pragma unroll
            for (int hh = 0; hh < 2; ++hh) {
                const int r = r0 + hh * 8;
                float v0 = acc[mi][ni][hh * 2], v1 = acc[mi][ni][hh * 2 + 1];
                if (EPI == 0) {
                    float2 f; f.x = v0 * alpha; f.y = v1 * alpha;
                    *(float2*)(obase + (size_t)r * ldc + c) = f;
                } else if (EPI == 1) {
                    uint32_t h2, l2; splitH2(v0, v1, h2, l2);
                    __half* o = cbase + (size_t)r * K3A + c;
                    *(uint32_t*)o = h2; *(uint32_t*)(o + 512) = h2; *(uint32_t*)(o + 1024) = l2;
                } else if (EPI == 4) {
                    uint32_t h2, l2; splitH2(v0, v1, h2, l2);
                    __half* o = cbase + (size_t)r * K2A + c;
                    *(uint32_t*)o = h2; *(uint32_t*)(o + 512) = h2;
                } else if (EPI == 3) {
                    v0 += pp.bias[z][c]; v1 += pp.bias[z][c + 1];
                    float2 f; f.x = v0; f.y = v1;
                    *(float2*)((float*)pp.out5[z] + (size_t)r * HID + c) = f;
                } else {   // EPI == 2
                    v0 += pp.bias[z][c]; v1 += pp.bias[z][c + 1];
                    uint32_t h2, l2; splitH2(v0, v1, h2, l2);
                    const int head = ((r >> 9) << 2) + (c >> 9);
                    __half* o = (__half*)pp.out5[z]
                        + ((size_t)(head * 512 + (r & 511))) * K3A + (c & 511);
                    *(uint32_t*)o = h2;
                    *(uint32_t*)(o + 512)  = modeB ? l2 : h2;
                    *(uint32_t*)(o + 1024) = modeB ? h2 : l2;
                }
            }
        }
}

// ------------------------- conversions -------------------------
__global__ void conv_x(const float* __restrict__ in, __half* __restrict__ x3)
{
    const int r = blockIdx.y;
    const int k = (blockIdx.x * blockDim.x + threadIdx.x) * 2;
    float2 x = *(const float2*)(in + (size_t)r * HID + k);
    uint32_t h2, l2; splitH2(x.x, x.y, h2, l2);
    __half* o3 = x3 + (size_t)r * K3P + k;
    *(uint32_t*)o3              = h2;
    *(uint32_t*)(o3 + HID)      = h2;
    *(uint32_t*)(o3 + 2 * HID)  = l2;
}

__global__ void conv_w(WPtr wp, __half* __restrict__ w3, __half* __restrict__ w2)
{
    const int w = blockIdx.z;
    const int r = blockIdx.y;
    const int k = (blockIdx.x * blockDim.x + threadIdx.x) * 2;
    float2 x = *(const float2*)(wp.w[w] + (size_t)r * HID + k);
    uint32_t h2, l2; splitH2(x.x, x.y, h2, l2);
    if (w < 3) {
        __half* o = w3 + ((size_t)w * HID + r) * K3P + k;
        *(uint32_t*)o             = h2;
        *(uint32_t*)(o + HID)     = l2;
        *(uint32_t*)(o + 2 * HID) = h2;
    } else {
        __half* o = w2 + ((size_t)(w - 3) * HID + r) * K2P + k;
        *(uint32_t*)o         = h2;
        *(uint32_t*)(o + HID) = l2;
    }
}

__global__ void convT2(const float* __restrict__ in, __half* __restrict__ out)
{
    __shared__ float t[32][33];
    const int r0 = blockIdx.y * 32, c0 = blockIdx.x * 32;
    const int tx = threadIdx.x, ty = threadIdx.y;
#pragma unroll
    for (int i = ty; i < 32; i += 8)
        t[i][tx] = in[(size_t)(r0 + i) * HID + c0 + tx];
    __syncthreads();
#pragma unroll
    for (int i = ty; i < 32; i += 8) {
        float x = t[tx][i];
        const int s = (r0 + tx) & 511;
        const int head = ((r0 >> 9) << 2) + ((c0 + i) >> 9);
        const int dd = (c0 + i) & 511;
        __half h = __float2half_rn(x);
        __half l = __float2half_rn(x - __half2float(h));
        __half* o = out + ((size_t)(head * 512 + dd)) * K2A + s;
        o[0] = h; o[512] = l;
    }
}

__global__ __launch_bounds__(128) void softmax_h(const float* __restrict__ S,
                                                 __half* __restrict__ P)
{
    const size_t row = blockIdx.x;
    const int t = threadIdx.x;
    float4 v = ((const float4*)(S + row * SQ))[t];
    float m = fmaxf(fmaxf(v.x, v.y), fmaxf(v.z, v.w));
#pragma unroll
    for (int o = 16; o; o >>= 1) m = fmaxf(m, __shfl_xor_sync(0xffffffffu, m, o));
    __shared__ float rm[4];
    if ((t & 31) == 0) rm[t >> 5] = m;
    __syncthreads();
    m = fmaxf(fmaxf(rm[0], rm[1]), fmaxf(rm[2], rm[3]));
    v.x = expf(v.x - m); v.y = expf(v.y - m); v.z = expf(v.z - m); v.w = expf(v.w - m);
    float s = v.x + v.y + v.z + v.w;
#pragma unroll
    for (int o = 16; o; o >>= 1) s += __shfl_xor_sync(0xffffffffu, s, o);
    __shared__ float rs[4];
    if ((t & 31) == 0) rs[t >> 5] = s;
    __syncthreads();
    s = rs[0] + rs[1] + rs[2] + rs[3];
    const float inv = 1.0f / s;
    __half2 h0, h1;
    h0.x = __float2half_rn(v.x * inv); h0.y = __float2half_rn(v.y * inv);
    h1.x = __float2half_rn(v.z * inv); h1.y = __float2half_rn(v.w * inv);
    __half* o = P + row * K2A + t * 4;
    *(__half2*)o         = h0; *(__half2*)(o + 2)   = h1;
    *(__half2*)(o + 512) = h0; *(__half2*)(o + 514) = h1;
}

// ------------------------- host -------------------------
extern "C" void kernel_launch(void* const* d_in, const int* in_sizes, int n_in,
                              void* d_out, int out_size)
{
    const float* X = (const float*)d_in[0];
    WPtr wp = {{(const float*)d_in[1], (const float*)d_in[3], (const float*)d_in[7],
                (const float*)d_in[5], (const float*)d_in[9]}};
    const float* bq  = (const float*)d_in[2];
    const float* bk  = (const float*)d_in[4];
    const float* bv  = (const float*)d_in[6];
    const float* bck = (const float*)d_in[8];
    const float* bcv = (const float*)d_in[10];

    void *x3, *w3, *w2, *ypv, *ypcv, *q3, *k3, *ck3, *vT2, *cvT2, *s13, *s2, *p2, *c2;
    cudaGetSymbolAddress(&x3, g_x3);
    cudaGetSymbolAddress(&w3, g_w3);     cudaGetSymbolAddress(&w2, g_w2);
    cudaGetSymbolAddress(&ypv, g_ypv);   cudaGetSymbolAddress(&ypcv, g_ypcv);
    cudaGetSymbolAddress(&q3, g_q3);     cudaGetSymbolAddress(&k3, g_k3);
    cudaGetSymbolAddress(&ck3, g_ck3);   cudaGetSymbolAddress(&vT2, g_vT2);
    cudaGetSymbolAddress(&cvT2, g_cvT2); cudaGetSymbolAddress(&s13, g_s13);
    cudaGetSymbolAddress(&s2, g_s2);     cudaGetSymbolAddress(&p2, g_p2);
    cudaGetSymbolAddress(&c2, g_c2);

    Ptrs pp3;
    pp3.bias[0] = bq;  pp3.out5[0] = q3;
    pp3.bias[1] = bk;  pp3.out5[1] = k3;
    pp3.bias[2] = bck; pp3.out5[2] = ck3;
    Ptrs pp2;
    pp2.bias[0] = bv;  pp2.out5[0] = ypv;
    pp2.bias[1] = bcv; pp2.out5[1] = ypcv;
    pp2.bias[2] = bv;  pp2.out5[2] = ypv;
    Ptrs pz = pp3;

    static bool init_done = false;
    static cudaStream_t sB;
    static cudaEvent_t evRoot, evB, evProj, evEnd;
    if (!init_done) {
        cudaFuncSetAttribute(gemm_mma<0>, cudaFuncAttributeMaxDynamicSharedMemorySize, SMEM_REQ);
        cudaFuncSetAttribute(gemm_mma<1>, cudaFuncAttributeMaxDynamicSharedMemorySize, SMEM_REQ);
        cudaFuncSetAttribute(gemm_mma<2>, cudaFuncAttributeMaxDynamicSharedMemorySize, SMEM_REQ);
        cudaFuncSetAttribute(gemm_mma<3>, cudaFuncAttributeMaxDynamicSharedMemorySize, SMEM_REQ);
        cudaFuncSetAttribute(gemm_mma<4>, cudaFuncAttributeMaxDynamicSharedMemorySize, SMEM_REQ);
        cudaStreamCreateWithFlags(&sB, cudaStreamNonBlocking);
        cudaEventCreateWithFlags(&evRoot, cudaEventDisableTiming);
        cudaEventCreateWithFlags(&evB, cudaEventDisableTiming);
        cudaEventCreateWithFlags(&evProj, cudaEventDisableTiming);
        cudaEventCreateWithFlags(&evEnd, cudaEventDisableTiming);
        init_done = true;
    }

    const long long s3 = (long long)SQ * K3A;
    const long long s2a = (long long)SQ * K2A;
    const size_t zo3  = (size_t)32 * SQ * K3A;   // head-group offset, cat3 bufs
    const size_t zo2  = (size_t)32 * SQ * K2A;   // cat2 bufs
    const size_t zoS  = (size_t)32 * SQ * SQ;    // fp32 s2
    const size_t zoO  = (size_t)8 * SQ * HID;    // d_out (8 batches)
    dim3 gh(SQ / 128, SQ / 128, 32);             // per-group attention grid

    // roots (default stream)
    conv_x<<<dim3(8, MR), 128>>>(X, (__half*)x3);
    conv_w<<<dim3(8, HID, 5), 128>>>(wp, (__half*)w3, (__half*)w2);
    cudaEventRecord(evRoot, 0);

    // branch B: proj2 (v,cv) + transposes
    cudaStreamWaitEvent(sB, evRoot, 0);
    gemm_mma<3><<<dim3(HID / 128, MR / 128, 2), 256, SMEM_REQ, sB>>>(
        (const __half*)x3, 0LL, K3P, (const __half*)w2, (long long)HID * K2P, K2P,
        nullptr, 1.0f, K2P, 0, 0, 0, 0, pp2);
    convT2<<<dim3(HID / 32, MR / 32), dim3(32, 8), 0, sB>>>((const float*)ypv, (__half*)vT2);
    convT2<<<dim3(HID / 32, MR / 32), dim3(32, 8), 0, sB>>>((const float*)ypcv, (__half*)cvT2);
    cudaEventRecord(evB, sB);

    // proj3 (default stream)
    gemm_mma<2><<<dim3(HID / 128, MR / 128, 3), 256, SMEM_REQ>>>(
        (const __half*)x3, 0LL, K3P, (const __half*)w3, (long long)HID * K3P, K3P,
        nullptr, 1.0f, K3P, 0, 0, 0, 0, pp3);
    cudaEventRecord(evProj, 0);

    // ----- group 1 (heads 32..63 = batches 8..15) on sB -----
    cudaStreamWaitEvent(sB, evProj, 0);
    gemm_mma<1><<<gh, 256, SMEM_REQ, sB>>>(
        (const __half*)q3 + zo3, s3, K3A, (const __half*)k3 + zo3, s3, K3A,
        (__half*)s13 + zo3, 1.0f, K3A, 0, 0, 0, 0, pz);
    gemm_mma<0><<<gh, 256, SMEM_REQ, sB>>>(
        (const __half*)s13 + zo3, s3, K3A, (const __half*)ck3 + zo3, s3, K3A,
        (float*)s2 + zoS, SCALE_F, K3A, (long long)SQ * SQ, 0, 0, SQ, pz);
    softmax_h<<<32 * SQ, 128, 0, sB>>>((const float*)s2 + zoS, (__half*)p2 + zo2);
    gemm_mma<4><<<gh, 256, SMEM_REQ, sB>>>(
        (const __half*)p2 + zo2, s2a, K2A, (const __half*)vT2 + zo2, s2a, K2A,
        (__half*)c2 + zo2, 1.0f, K2A, 0, 0, 0, 0, pz);
    gemm_mma<0><<<gh, 256, SMEM_REQ, sB>>>(
        (const __half*)c2 + zo2, s2a, K2A, (const __half*)cvT2 + zo2, s2a, K2A,
        (float*)d_out + zoO, 1.0f, K2A, 0, (long long)SQ * HID, 512, HID, pz);
    cudaEventRecord(evEnd, sB);

    // ----- group 0 (heads 0..31 = batches 0..7) on default stream -----
    gemm_mma<1><<<gh, 256, SMEM_REQ>>>(
        (const __half*)q3, s3, K3A, (const __half*)k3, s3, K3A,
        s13, 1.0f, K3A, 0, 0, 0, 0, pz);
    gemm_mma<0><<<gh, 256, SMEM_REQ>>>(
        (const __half*)s13, s3, K3A, (const __half*)ck3, s3, K3A,
        s2, SCALE_F, K3A, (long long)SQ * SQ, 0, 0, SQ, pz);
    softmax_h<<<32 * SQ, 128>>>((const float*)s2, (__half*)p2);
    cudaStreamWaitEvent(0, evB, 0);
    gemm_mma<4><<<gh, 256, SMEM_REQ>>>(
        (const __half*)p2, s2a, K2A, (const __half*)vT2, s2a, K2A,
        c2, 1.0f, K2A, 0, 0, 0, 0, pz);
    gemm_mma<0><<<gh, 256, SMEM_REQ>>>(
        (const __half*)c2, s2a, K2A, (const __half*)cvT2, s2a, K2A,
        d_out, 1.0f, K2A, 0, (long long)SQ * HID, 512, HID, pz);

    // join sB back into the harness's stream
    cudaStreamWaitEvent(0, evEnd, 0);
}